// round 1
// baseline (speedup 1.0000x reference)
#include <cuda_runtime.h>

#define N_NODES 50000
#define IN_DIM 256
#define OUT_DIM 128
#define NNZ_X 800000
#define N_EDGES 1600000

// scratch for intermediate h = X @ W  (25.6 MB) — __device__ global, no allocs
__device__ float g_h[N_NODES * OUT_DIM];

__global__ void zero_kernel(float* __restrict__ out) {
    const int total = N_NODES * OUT_DIM;
    int idx = blockIdx.x * blockDim.x + threadIdx.x;
    int stride = gridDim.x * blockDim.x;
    for (int i = idx; i < total; i += stride) {
        g_h[i] = 0.0f;
        out[i] = 0.0f;
    }
}

// hop 1: h[row] += (val * mask) * W[col]   (warp per nonzero, lane owns 4 cols)
__global__ void spmm_xw_kernel(const int* __restrict__ rows,
                               const int* __restrict__ cols,
                               const float* __restrict__ vals,
                               const float* __restrict__ noise,
                               const float* __restrict__ W) {
    int gw = (blockIdx.x * blockDim.x + threadIdx.x) >> 5;
    int lane = threadIdx.x & 31;
    if (gw >= NNZ_X) return;
    int r = rows[gw];
    int c = cols[gw];
    float v = vals[gw] * floorf(1.0f + noise[gw]);  // keep_prob=1.0 -> mask==1
    float4 w = reinterpret_cast<const float4*>(W + c * OUT_DIM)[lane];
    float* dst = g_h + (size_t)r * OUT_DIM + lane * 4;
    atomicAdd(dst + 0, v * w.x);
    atomicAdd(dst + 1, v * w.y);
    atomicAdd(dst + 2, v * w.z);
    atomicAdd(dst + 3, v * w.w);
}

// hop 2: out[row] += w * h[col]   (warp per edge)
__global__ void spmm_adj_kernel(const int* __restrict__ rows,
                                const int* __restrict__ cols,
                                const float* __restrict__ wvals,
                                float* __restrict__ out) {
    int gw = (blockIdx.x * blockDim.x + threadIdx.x) >> 5;
    int lane = threadIdx.x & 31;
    if (gw >= N_EDGES) return;
    int r = rows[gw];
    int c = cols[gw];
    float v = wvals[gw];
    float4 h4 = reinterpret_cast<const float4*>(g_h + (size_t)c * OUT_DIM)[lane];
    float* dst = out + (size_t)r * OUT_DIM + lane * 4;
    atomicAdd(dst + 0, v * h4.x);
    atomicAdd(dst + 1, v * h4.y);
    atomicAdd(dst + 2, v * h4.z);
    atomicAdd(dst + 3, v * h4.w);
}

__global__ void relu_kernel(float* __restrict__ out) {
    const int total = N_NODES * OUT_DIM;
    int idx = blockIdx.x * blockDim.x + threadIdx.x;
    int stride = gridDim.x * blockDim.x;
    for (int i = idx; i < total; i += stride)
        out[i] = fmaxf(out[i], 0.0f);
}

extern "C" void kernel_launch(void* const* d_in, const int* in_sizes, int n_in,
                              void* d_out, int out_size) {
    const int*   x_rows   = (const int*)d_in[0];
    const int*   x_cols   = (const int*)d_in[1];
    const float* x_vals   = (const float*)d_in[2];
    const float* noise    = (const float*)d_in[3];
    const int*   adj_rows = (const int*)d_in[4];
    const int*   adj_cols = (const int*)d_in[5];
    const float* adj_vals = (const float*)d_in[6];
    const float* W        = (const float*)d_in[7];
    float* out = (float*)d_out;

    zero_kernel<<<592, 256>>>(out);

    // warp per nonzero: 800k warps -> 100000 blocks of 8 warps
    spmm_xw_kernel<<<(NNZ_X * 32 + 255) / 256, 256>>>(x_rows, x_cols, x_vals, noise, W);

    // warp per edge: 1.6M warps -> 200000 blocks
    spmm_adj_kernel<<<(N_EDGES * 32 + 255) / 256, 256>>>(adj_rows, adj_cols, adj_vals, out);

    relu_kernel<<<592, 256>>>(out);
}

// round 2
// speedup vs baseline: 2.9776x; 2.9776x over previous
#include <cuda_runtime.h>

#define N_NODES 50000
#define IN_DIM 256
#define OUT_DIM 128
#define NNZ_X 800000
#define N_EDGES 1600000

// scratch for intermediate h = X @ W  (25.6 MB) — __device__ global, no allocs
__device__ float g_h[N_NODES * OUT_DIM];

__device__ __forceinline__ void red_add_v4(float* ptr, float a, float b, float c, float d) {
    asm volatile("red.global.add.v4.f32 [%0], {%1,%2,%3,%4};"
                 :: "l"(ptr), "f"(a), "f"(b), "f"(c), "f"(d) : "memory");
}

__global__ void zero_kernel(float4* __restrict__ out) {
    const int total = N_NODES * OUT_DIM / 4;
    float4* h4 = reinterpret_cast<float4*>(g_h);
    const float4 z = make_float4(0.f, 0.f, 0.f, 0.f);
    int idx = blockIdx.x * blockDim.x + threadIdx.x;
    int stride = gridDim.x * blockDim.x;
    for (int i = idx; i < total; i += stride) {
        h4[i] = z;
        out[i] = z;
    }
}

// hop 1: h[row] += (val * mask) * W[col]
// warp per 4 nonzeros; lane owns 4 of 128 output cols (float4)
__global__ void spmm_xw_kernel(const int* __restrict__ rows,
                               const int* __restrict__ cols,
                               const float* __restrict__ vals,
                               const float* __restrict__ noise,
                               const float* __restrict__ W) {
    int gw = (blockIdx.x * blockDim.x + threadIdx.x) >> 5;   // warp id = group of 4 nnz
    int lane = threadIdx.x & 31;
    int base = gw * 4;
    if (base >= NNZ_X) return;

    int   r[4], c[4];
    float v[4];
    float4 w[4];
#pragma unroll
    for (int k = 0; k < 4; k++) {
        int e = base + k;
        r[k] = rows[e];
        c[k] = cols[e];
        v[k] = vals[e] * floorf(1.0f + noise[e]);   // keep_prob=1.0 -> mask==1
        w[k] = reinterpret_cast<const float4*>(W + c[k] * OUT_DIM)[lane];
    }
#pragma unroll
    for (int k = 0; k < 4; k++) {
        float* dst = g_h + (size_t)r[k] * OUT_DIM + lane * 4;
        red_add_v4(dst, v[k] * w[k].x, v[k] * w[k].y, v[k] * w[k].z, v[k] * w[k].w);
    }
}

// hop 2: out[row] += w * h[col]   (warp per 4 edges)
__global__ void spmm_adj_kernel(const int* __restrict__ rows,
                                const int* __restrict__ cols,
                                const float* __restrict__ wvals,
                                float* __restrict__ out) {
    int gw = (blockIdx.x * blockDim.x + threadIdx.x) >> 5;
    int lane = threadIdx.x & 31;
    int base = gw * 4;
    if (base >= N_EDGES) return;

    int   r[4], c[4];
    float v[4];
    float4 h4[4];
#pragma unroll
    for (int k = 0; k < 4; k++) {
        int e = base + k;
        r[k] = rows[e];
        c[k] = cols[e];
        v[k] = wvals[e];
        h4[k] = reinterpret_cast<const float4*>(g_h + (size_t)c[k] * OUT_DIM)[lane];
    }
#pragma unroll
    for (int k = 0; k < 4; k++) {
        float* dst = out + (size_t)r[k] * OUT_DIM + lane * 4;
        red_add_v4(dst, v[k] * h4[k].x, v[k] * h4[k].y, v[k] * h4[k].z, v[k] * h4[k].w);
    }
}

__global__ void relu_kernel(float4* __restrict__ out) {
    const int total = N_NODES * OUT_DIM / 4;
    int idx = blockIdx.x * blockDim.x + threadIdx.x;
    int stride = gridDim.x * blockDim.x;
    for (int i = idx; i < total; i += stride) {
        float4 t = out[i];
        t.x = fmaxf(t.x, 0.f);
        t.y = fmaxf(t.y, 0.f);
        t.z = fmaxf(t.z, 0.f);
        t.w = fmaxf(t.w, 0.f);
        out[i] = t;
    }
}

extern "C" void kernel_launch(void* const* d_in, const int* in_sizes, int n_in,
                              void* d_out, int out_size) {
    const int*   x_rows   = (const int*)d_in[0];
    const int*   x_cols   = (const int*)d_in[1];
    const float* x_vals   = (const float*)d_in[2];
    const float* noise    = (const float*)d_in[3];
    const int*   adj_rows = (const int*)d_in[4];
    const int*   adj_cols = (const int*)d_in[5];
    const float* adj_vals = (const float*)d_in[6];
    const float* W        = (const float*)d_in[7];
    float* out = (float*)d_out;

    zero_kernel<<<592, 256>>>(reinterpret_cast<float4*>(out));

    // warp per 4 nonzeros: 200k warps
    spmm_xw_kernel<<<(NNZ_X / 4 * 32 + 255) / 256, 256>>>(x_rows, x_cols, x_vals, noise, W);

    // warp per 4 edges: 400k warps
    spmm_adj_kernel<<<(N_EDGES / 4 * 32 + 255) / 256, 256>>>(adj_rows, adj_cols, adj_vals, out);

    relu_kernel<<<592, 256>>>(reinterpret_cast<float4*>(out));
}